// round 13
// baseline (speedup 1.0000x reference)
#include <cuda_runtime.h>
#include <cstdint>

#define BATCH  8
#define HWDIM  64
#define CCH    256
#define RED    64
#define EE     144     // K*K*G = 9*16
#define NPIX   32768

// ---- device scratch ----
__device__ uint32_t g_midh[NPIX * 32];          // mid hi planes (bf16x2, [px][32w]) 4MB
__device__ uint32_t g_midl[NPIX * 32];          // mid lo planes 4MB
__device__ float    g_wgt[(size_t)NPIX * EE];   // wgt fp32 [px][144] 18.9MB

// m16n8k16 bf16 mma
__device__ __forceinline__ void mma_bf16(float d[4],
    uint32_t a0, uint32_t a1, uint32_t a2, uint32_t a3,
    uint32_t b0, uint32_t b1)
{
    asm volatile(
        "mma.sync.aligned.m16n8k16.row.col.f32.bf16.bf16.f32 "
        "{%0,%1,%2,%3}, {%4,%5,%6,%7}, {%8,%9}, {%0,%1,%2,%3};"
        : "+f"(d[0]), "+f"(d[1]), "+f"(d[2]), "+f"(d[3])
        : "r"(a0), "r"(a1), "r"(a2), "r"(a3), "r"(b0), "r"(b1));
}

__device__ __forceinline__ void bf16_split_pair(float v0, float v1,
                                                uint32_t& hi, uint32_t& lo)
{
    uint32_t h;
    asm("cvt.rn.bf16x2.f32 %0, %1, %2;" : "=r"(h) : "f"(v1), "f"(v0));
    float h0 = __uint_as_float(h << 16);
    float h1 = __uint_as_float(h & 0xFFFF0000u);
    float l0 = v0 - h0;
    float l1 = v1 - h1;
    asm("cvt.rn.bf16x2.f32 %0, %1, %2;" : "=r"(lo) : "f"(l1), "f"(l0));
    hi = h;
}

// ============================================================
// K1: mid = x @ W1 + b1   -> bf16 hi/lo planes in gmem
// grid 512 x 64px, 256 thr, 8 warps = (mt 0..3) x (nh 0..1)
// ============================================================
#define K1_W1H 0
#define K1_W1L 8448
#define K1_WORDS 16896
#define W1P_STRIDE 132

__global__ void __launch_bounds__(256, 2)
gemm1_kernel(const float* __restrict__ x,
             const float* __restrict__ W1,
             const float* __restrict__ b1)
{
    extern __shared__ uint32_t su[];
    const int t = threadIdx.x;

    // W1 -> interleaved bf16 planes [n][s*8 + 2*(p&3) + (p>>2)]
    #pragma unroll
    for (int it = 0; it < 4; it++) {
        int u = t + it * 256;              // 1024 units: (n, k16-step)
        int n  = u & 63;
        int st = u >> 6;
        float v[16];
        #pragma unroll
        for (int j = 0; j < 16; j++) v[j] = W1[(st * 16 + j) * RED + n];
        uint32_t h[8], l[8];
        #pragma unroll
        for (int p = 0; p < 8; p++) bf16_split_pair(v[2*p], v[2*p+1], h[p], l[p]);
        int base = n * W1P_STRIDE + st * 8;
        *(uint4*)(su + K1_W1H + base)     = make_uint4(h[0], h[4], h[1], h[5]);
        *(uint4*)(su + K1_W1H + base + 4) = make_uint4(h[2], h[6], h[3], h[7]);
        *(uint4*)(su + K1_W1L + base)     = make_uint4(l[0], l[4], l[1], l[5]);
        *(uint4*)(su + K1_W1L + base + 4) = make_uint4(l[2], l[6], l[3], l[7]);
    }
    __syncthreads();

    const int warp = t >> 5, lane = t & 31;
    const int gid = lane >> 2, t4 = lane & 3;
    const int m0 = (warp >> 1) * 16;
    const int nh = warp & 1;               // ntiles j = nh*4 .. nh*4+3
    const int pxb = blockIdx.x * 64;

    const float* xr0 = x + (size_t)(pxb + m0 + gid) * CCH + 2 * t4;
    const float* xr1 = xr0 + 8 * CCH;

    float Dm[4][4], Dc[4][4];
    #pragma unroll
    for (int j = 0; j < 4; j++)
        #pragma unroll
        for (int i = 0; i < 4; i++) { Dm[j][i] = 0.f; Dc[j][i] = 0.f; }

    float2 c0 = *(const float2*)(xr0);
    float2 c1 = *(const float2*)(xr1);
    float2 c2 = *(const float2*)(xr0 + 8);
    float2 c3 = *(const float2*)(xr1 + 8);

    #pragma unroll 4
    for (int k0 = 0; k0 < CCH; k0 += 16) {
        float2 n0, n1, n2, n3;
        if (k0 + 16 < CCH) {
            n0 = *(const float2*)(xr0 + k0 + 16);
            n1 = *(const float2*)(xr1 + k0 + 16);
            n2 = *(const float2*)(xr0 + k0 + 24);
            n3 = *(const float2*)(xr1 + k0 + 24);
        }
        uint32_t ah[4], al[4];
        bf16_split_pair(c0.x, c0.y, ah[0], al[0]);
        bf16_split_pair(c1.x, c1.y, ah[1], al[1]);
        bf16_split_pair(c2.x, c2.y, ah[2], al[2]);
        bf16_split_pair(c3.x, c3.y, ah[3], al[3]);
        const int sw = (k0 >> 1) + 2 * t4;
        #pragma unroll
        for (int jj = 0; jj < 4; jj++) {
            int n = (nh * 4 + jj) * 8 + gid;
            uint2 bh = *(const uint2*)(su + K1_W1H + n * W1P_STRIDE + sw);
            uint2 bl = *(const uint2*)(su + K1_W1L + n * W1P_STRIDE + sw);
            mma_bf16(Dm[jj], ah[0], ah[1], ah[2], ah[3], bh.x, bh.y);
            mma_bf16(Dc[jj], al[0], al[1], al[2], al[3], bh.x, bh.y);
            mma_bf16(Dc[jj], ah[0], ah[1], ah[2], ah[3], bl.x, bl.y);
        }
        c0 = n0; c1 = n1; c2 = n2; c3 = n3;
    }

    // epilogue -> mid planes ([px][32w], word w = (j>>1)*8 + 2*t4 + (j&1))
    #pragma unroll
    for (int jj = 0; jj < 4; jj++) {
        int j  = nh * 4 + jj;
        int n0 = j * 8 + 2 * t4;
        float bia0 = __ldg(b1 + n0), bia1 = __ldg(b1 + n0 + 1);
        int w = (j >> 1) * 8 + 2 * t4 + (j & 1);
        uint32_t h, l;
        bf16_split_pair(Dm[jj][0] + Dc[jj][0] + bia0,
                        Dm[jj][1] + Dc[jj][1] + bia1, h, l);
        g_midh[(pxb + m0 + gid) * 32 + w] = h;
        g_midl[(pxb + m0 + gid) * 32 + w] = l;
        bf16_split_pair(Dm[jj][2] + Dc[jj][2] + bia0,
                        Dm[jj][3] + Dc[jj][3] + bia1, h, l);
        g_midh[(pxb + m0 + gid + 8) * 32 + w] = h;
        g_midl[(pxb + m0 + gid + 8) * 32 + w] = l;
    }
}

// ============================================================
// K2: wgt = mid @ W2 + b2  -> fp32 [px][144]
// grid 512 x 64px, 256 thr, 8 warps = (mt 0..3) x (nhalf 0..1), 9 ntiles each
// ============================================================
#define K2_W2H 0
#define K2_W2L 5184
#define K2_WORDS 10368
#define W2P_STRIDE 36

__global__ void __launch_bounds__(256, 2)
gemm2_kernel(const float* __restrict__ W2, const float* __restrict__ b2)
{
    extern __shared__ uint32_t su[];
    const int t = threadIdx.x;

    // W2 -> interleaved bf16 planes [e][s*8 + ...]  (576 units)
    #pragma unroll
    for (int it = 0; it < 3; it++) {
        int u = t + it * 256;
        if (u < 576) {
            int st = u / 144;
            int e  = u - st * 144;
            float v[16];
            #pragma unroll
            for (int j = 0; j < 16; j++) v[j] = W2[(st * 16 + j) * EE + e];
            uint32_t h[8], l[8];
            #pragma unroll
            for (int p = 0; p < 8; p++) bf16_split_pair(v[2*p], v[2*p+1], h[p], l[p]);
            int base = e * W2P_STRIDE + st * 8;
            *(uint4*)(su + K2_W2H + base)     = make_uint4(h[0], h[4], h[1], h[5]);
            *(uint4*)(su + K2_W2H + base + 4) = make_uint4(h[2], h[6], h[3], h[7]);
            *(uint4*)(su + K2_W2L + base)     = make_uint4(l[0], l[4], l[1], l[5]);
            *(uint4*)(su + K2_W2L + base + 4) = make_uint4(l[2], l[6], l[3], l[7]);
        }
    }
    __syncthreads();

    const int warp = t >> 5, lane = t & 31;
    const int gid = lane >> 2, t4 = lane & 3;
    const int m0 = (warp >> 1) * 16;
    const int nhalf = warp & 1;            // ntiles j = nhalf*9 .. +8
    const int pxb = blockIdx.x * 64;

    const uint32_t* mh0 = g_midh + (size_t)(pxb + m0 + gid) * 32 + 2 * t4;
    const uint32_t* mh1 = mh0 + 8 * 32;
    const uint32_t* ml0 = g_midl + (size_t)(pxb + m0 + gid) * 32 + 2 * t4;
    const uint32_t* ml1 = ml0 + 8 * 32;

    float Dm[9][4], Dc[9][4];
    #pragma unroll
    for (int j = 0; j < 9; j++)
        #pragma unroll
        for (int i = 0; i < 4; i++) { Dm[j][i] = 0.f; Dc[j][i] = 0.f; }

    uint2 ch0 = *(const uint2*)(mh0);
    uint2 ch1 = *(const uint2*)(mh1);
    uint2 cl0 = *(const uint2*)(ml0);
    uint2 cl1 = *(const uint2*)(ml1);

    #pragma unroll
    for (int s = 0; s < 4; s++) {          // k0 = s*16
        uint2 nh0, nh1, nl0, nl1;
        if (s < 3) {
            nh0 = *(const uint2*)(mh0 + (s + 1) * 8);
            nh1 = *(const uint2*)(mh1 + (s + 1) * 8);
            nl0 = *(const uint2*)(ml0 + (s + 1) * 8);
            nl1 = *(const uint2*)(ml1 + (s + 1) * 8);
        }
        const int sw = s * 8 + 2 * t4;
        #pragma unroll
        for (int jj = 0; jj < 9; jj++) {
            int e = (nhalf * 9 + jj) * 8 + gid;
            uint2 bh = *(const uint2*)(su + K2_W2H + e * W2P_STRIDE + sw);
            uint2 bl = *(const uint2*)(su + K2_W2L + e * W2P_STRIDE + sw);
            mma_bf16(Dm[jj], ch0.x, ch1.x, ch0.y, ch1.y, bh.x, bh.y);
            mma_bf16(Dc[jj], cl0.x, cl1.x, cl0.y, cl1.y, bh.x, bh.y);
            mma_bf16(Dc[jj], ch0.x, ch1.x, ch0.y, ch1.y, bl.x, bl.y);
        }
        ch0 = nh0; ch1 = nh1; cl0 = nl0; cl1 = nl1;
    }

    #pragma unroll
    for (int jj = 0; jj < 9; jj++) {
        int j  = nhalf * 9 + jj;
        int e0 = j * 8 + 2 * t4;
        float bb0 = __ldg(b2 + e0), bb1 = __ldg(b2 + e0 + 1);
        *(float2*)(g_wgt + (size_t)(pxb + m0 + gid) * EE + e0) =
            make_float2(Dm[jj][0] + Dc[jj][0] + bb0, Dm[jj][1] + Dc[jj][1] + bb1);
        *(float2*)(g_wgt + (size_t)(pxb + m0 + gid + 8) * EE + e0) =
            make_float2(Dm[jj][2] + Dc[jj][2] + bb0, Dm[jj][3] + Dc[jj][3] + bb1);
    }
}

// ============================================================
// K3: involution. tile 8x4, 256 thr, 8 warps = tile rows.
// ============================================================
#define HALO_W 6
#define XH_STRIDE 260
#define OFF_XH 0                       // 60*260 = 15600
#define OFF_WG 15600                   // 32*145 = 4640
#define WGT_STRIDE 145
#define K3_WORDS 20240
#define K3_BYTES (K3_WORDS * 4)        // 80960 B -> 2 CTAs/SM

__global__ void __launch_bounds__(256, 2)
invo_kernel(const float* __restrict__ x, float* __restrict__ out)
{
    extern __shared__ float s[];
    const int t  = threadIdx.x;
    const int bb = blockIdx.z;
    const int h0 = blockIdx.y * 8;
    const int w0 = blockIdx.x * 4;

    // halo 10x6 x 256 (zero-padded)
    #pragma unroll
    for (int it = 0; it < 15; it++) {
        int i4 = t + it * 256;             // 0..3839 float4s
        int c4 = i4 & 63;
        int sp = i4 >> 6;                  // 0..59
        int r  = sp / HALO_W;
        int cl = sp - r * HALO_W;
        int gh = h0 - 1 + r;
        int gw = w0 - 1 + cl;
        float4 v = make_float4(0.f, 0.f, 0.f, 0.f);
        if ((unsigned)gh < HWDIM && (unsigned)gw < HWDIM)
            v = *(const float4*)(x + ((size_t)((bb * HWDIM + gh) * HWDIM + gw) * CCH) + c4 * 4);
        *(float4*)(s + OFF_XH + sp * XH_STRIDE + c4 * 4) = v;
    }
    // wgt tile: 8 gmem rows of 4px*144 contiguous floats -> smem stride 145
    #pragma unroll
    for (int it = 0; it < 18; it++) {
        int i = t + it * 256;              // 0..4607
        int r = i / 576;
        int o = i - r * 576;
        int pc = o / 144;
        int e  = o - pc * 144;
        float v = g_wgt[((size_t)((bb * HWDIM + h0 + r) * HWDIM + w0)) * EE + o];
        s[OFF_WG + (r * 4 + pc) * WGT_STRIDE + e] = v;
    }
    __syncthreads();

    // stage3: warp = tile row pr; lane: gset = lane>>2 (0..7), pc = lane&3
    {
        const int warp = t >> 5, lane = t & 31;
        const int pr = warp;
        const int gset = lane >> 2, pc = lane & 3;
        const int wbase = OFF_WG + (pr * 4 + pc) * WGT_STRIDE;
        const int xb = OFF_XH + (pr * HALO_W + pc) * XH_STRIDE;  // tap (0,0)
        float* op = out + ((size_t)((bb * HWDIM + h0 + pr) * HWDIM + (w0 + pc))) * CCH;
        #pragma unroll
        for (int gi = 0; gi < 2; gi++) {
            int g = gset * 2 + gi;
            float wv[9];
            #pragma unroll
            for (int k = 0; k < 9; k++) wv[k] = s[wbase + g * 9 + k];
            int F0g = g * 36;
            int ko0 = F0g >> 6;
            int cs0 = F0g & 63;
            int tc  = 64 - cs0;
            int di0 = (ko0 * 11) >> 5, dj0 = ko0 - 3 * di0;
            int ko1 = ko0 + 1;
            int di1 = (ko1 * 11) >> 5, dj1 = ko1 - 3 * di1;
            int A0 = xb + (di0 * HALO_W + dj0) * XH_STRIDE + cs0 * 4;
            int A1 = xb + (di1 * HALO_W + dj1) * XH_STRIDE - tc * 4;
            #pragma unroll
            for (int c = 0; c < 4; c++) {
                float acc[4] = {0.f, 0.f, 0.f, 0.f};
                #pragma unroll
                for (int j = 0; j < 9; j++) {
                    const int idx = c * 9 + j;
                    int addr = ((idx < tc) ? A0 : A1) + idx * 4;
                    const float4 xv = *(const float4*)(s + addr);
                    const int fl = idx * 4;
                    acc[(fl + 0) / 9 - c * 4] += wv[(fl + 0) % 9] * xv.x;
                    acc[(fl + 1) / 9 - c * 4] += wv[(fl + 1) % 9] * xv.y;
                    acc[(fl + 2) / 9 - c * 4] += wv[(fl + 2) % 9] * xv.z;
                    acc[(fl + 3) / 9 - c * 4] += wv[(fl + 3) % 9] * xv.w;
                }
                *(float4*)(op + g * 16 + c * 4) =
                    make_float4(acc[0], acc[1], acc[2], acc[3]);
            }
        }
    }
}

// ============================================================
extern "C" void kernel_launch(void* const* d_in, const int* in_sizes, int n_in,
                              void* d_out, int out_size)
{
    (void)in_sizes; (void)n_in; (void)out_size;
    const float* x  = (const float*)d_in[0];
    const float* W1 = (const float*)d_in[1];
    const float* b1 = (const float*)d_in[2];
    const float* W2 = (const float*)d_in[3];
    const float* b2 = (const float*)d_in[4];
    float* out = (float*)d_out;

    cudaFuncSetAttribute(gemm1_kernel, cudaFuncAttributeMaxDynamicSharedMemorySize, K1_WORDS * 4);
    cudaFuncSetAttribute(gemm2_kernel, cudaFuncAttributeMaxDynamicSharedMemorySize, K2_WORDS * 4);
    cudaFuncSetAttribute(invo_kernel,  cudaFuncAttributeMaxDynamicSharedMemorySize, K3_BYTES);

    gemm1_kernel<<<NPIX / 64, 256, K1_WORDS * 4>>>(x, W1, b1);
    gemm2_kernel<<<NPIX / 64, 256, K2_WORDS * 4>>>(W2, b2);
    dim3 grid(HWDIM / 4, HWDIM / 8, BATCH);   // (16, 8, 8) = 1024 CTAs
    invo_kernel<<<grid, 256, K3_BYTES>>>(x, out);
}

// round 14
// speedup vs baseline: 1.2501x; 1.2501x over previous
#include <cuda_runtime.h>
#include <cstdint>

#define BATCH  8
#define HWDIM  64
#define CCH    256
#define RED    64
#define EE     144     // K*K*G = 9*16
#define NTHR   512

// ---- smem layout (32-bit word offsets) ----
#define XH_STRIDE  260
#define OFF_XH     0                    // 100*260 = 26000 (fp32)
#define OFF_W1H    26000                // 64*132 = 8448 (bf16x2, [n][k/2])
#define W1P_STRIDE 132
#define OFF_W1L    34448                // 8448 ; planes end 42896
#define OFF_WGT    26000                // overlay W1 planes after stage1: 64*145 = 9280
#define WGT_STRIDE 145
#define OFF_W2H    42896                // 144*36 = 5184 ([e][d/2])
#define W2P_STRIDE 36
#define OFF_W2L    48080                // 5184 ; end 53264
#define OFF_MID    53264                // 64*68 = 4352 (fp32)
#define MID_STRIDE 68
#define OFF_B1     57616                // 64
#define OFF_B2     57680                // 144
#define SMEM_WORDS 57824
#define SMEM_BYTES (SMEM_WORDS * 4)     // 231296 B, 1 CTA/SM

// m16n8k16 bf16 mma
__device__ __forceinline__ void mma_bf16(float d[4],
    uint32_t a0, uint32_t a1, uint32_t a2, uint32_t a3,
    uint32_t b0, uint32_t b1)
{
    asm volatile(
        "mma.sync.aligned.m16n8k16.row.col.f32.bf16.bf16.f32 "
        "{%0,%1,%2,%3}, {%4,%5,%6,%7}, {%8,%9}, {%0,%1,%2,%3};"
        : "+f"(d[0]), "+f"(d[1]), "+f"(d[2]), "+f"(d[3])
        : "r"(a0), "r"(a1), "r"(a2), "r"(a3), "r"(b0), "r"(b1));
}

__device__ __forceinline__ void bf16_split_pair(float v0, float v1,
                                                uint32_t& hi, uint32_t& lo)
{
    uint32_t h;
    asm("cvt.rn.bf16x2.f32 %0, %1, %2;" : "=r"(h) : "f"(v1), "f"(v0));
    float h0 = __uint_as_float(h << 16);
    float h1 = __uint_as_float(h & 0xFFFF0000u);
    float l0 = v0 - h0;
    float l1 = v1 - h1;
    asm("cvt.rn.bf16x2.f32 %0, %1, %2;" : "=r"(lo) : "f"(l1), "f"(l0));
    hi = h;
}

__device__ __forceinline__ void cp_async16(uint32_t daddr, const void* src, int sz)
{
    asm volatile("cp.async.cg.shared.global [%0], [%1], 16, %2;"
                 :: "r"(daddr), "l"(src), "r"(sz));
}

__global__ void __launch_bounds__(NTHR, 1)
invo_mma_kernel(const float* __restrict__ x,
                const float* __restrict__ W1,
                const float* __restrict__ b1,
                const float* __restrict__ W2,
                const float* __restrict__ b2,
                float* __restrict__ out)
{
    extern __shared__ float s[];
    uint32_t* su = (uint32_t*)s;
    const int t  = threadIdx.x;
    const int bb = blockIdx.z;
    const int h0 = blockIdx.y * 8;
    const int w0 = blockIdx.x * 8;

    uint32_t s_base;
    asm("{ .reg .u64 tt; cvta.to.shared.u64 tt, %1; cvt.u32.u64 %0, tt; }"
        : "=r"(s_base) : "l"(s));

    // ---- Phase 0a-1: CENTER 8x8x256 via cp.async (always in-bounds) -> group 0 ----
    #pragma unroll
    for (int it = 0; it < 8; it++) {
        int i4 = t + it * NTHR;            // 0..4095
        int c4 = i4 & 63;
        int u  = i4 >> 6;                  // 0..63
        int r  = (u >> 3) + 1;
        int cl = (u & 7) + 1;
        int sp = r * 10 + cl;
        const float* gp = x + ((size_t)((bb * HWDIM + h0 + (u >> 3)) * HWDIM
                                        + (w0 + (u & 7))) * CCH) + c4 * 4;
        cp_async16(s_base + (OFF_XH + sp * XH_STRIDE + c4 * 4) * 4, gp, 16);
    }
    asm volatile("cp.async.commit_group;" ::: "memory");

    // ---- Phase 0a-2: RING 36 positions (zero-fill OOB) -> group 1 ----
    #pragma unroll
    for (int it = 0; it < 5; it++) {
        int i4 = t + it * NTHR;            // 0..2303
        if (i4 < 2304) {
            int c4 = i4 & 63;
            int p  = i4 >> 6;              // 0..35
            int r, cl;
            if (p < 10)      { r = 0; cl = p; }
            else if (p < 20) { r = 9; cl = p - 10; }
            else             { int q = p - 20; r = 1 + (q >> 1); cl = (q & 1) * 9; }
            int gh = h0 - 1 + r;
            int gw = w0 - 1 + cl;
            bool ok = ((unsigned)gh < HWDIM) && ((unsigned)gw < HWDIM);
            const float* gp = ok
                ? x + ((size_t)((bb * HWDIM + gh) * HWDIM + gw) * CCH) + c4 * 4
                : x;
            cp_async16(s_base + (OFF_XH + (r * 10 + cl) * XH_STRIDE + c4 * 4) * 4,
                       gp, ok ? 16 : 0);
        }
    }
    asm volatile("cp.async.commit_group;" ::: "memory");

    // ---- Phase 0b: W1 -> bf16 hi/lo planes [n][k/2] (sequential words) ----
    #pragma unroll
    for (int it = 0; it < 4; it++) {
        int u = t + it * NTHR;             // 2048 units: (n, k-octet)
        int n  = u & 63;
        int ko = u >> 6;                   // 0..31, k0 = ko*8
        float v[8];
        #pragma unroll
        for (int j = 0; j < 8; j++) v[j] = W1[(ko * 8 + j) * RED + n];
        uint32_t h[4], l[4];
        #pragma unroll
        for (int p = 0; p < 4; p++) bf16_split_pair(v[2*p], v[2*p+1], h[p], l[p]);
        int base = n * W1P_STRIDE + ko * 4;
        *(uint4*)(su + OFF_W1H + base) = make_uint4(h[0], h[1], h[2], h[3]);
        *(uint4*)(su + OFF_W1L + base) = make_uint4(l[0], l[1], l[2], l[3]);
    }
    // ---- Phase 0c: W2 -> bf16 hi/lo planes [e][d/2] (1152 octet-units) ----
    #pragma unroll
    for (int it = 0; it < 3; it++) {
        int u = t + it * NTHR;
        if (u < 1152) {
            int dko = u / 144;             // 0..7
            int e   = u - dko * 144;
            float v[8];
            #pragma unroll
            for (int j = 0; j < 8; j++) v[j] = W2[(dko * 8 + j) * EE + e];
            uint32_t h[4], l[4];
            #pragma unroll
            for (int p = 0; p < 4; p++) bf16_split_pair(v[2*p], v[2*p+1], h[p], l[p]);
            int base = e * W2P_STRIDE + dko * 4;
            *(uint4*)(su + OFF_W2H + base) = make_uint4(h[0], h[1], h[2], h[3]);
            *(uint4*)(su + OFF_W2L + base) = make_uint4(l[0], l[1], l[2], l[3]);
        }
    }
    if (t < RED) s[OFF_B1 + t] = b1[t];
    else if (t >= 128 && t < 128 + EE) s[OFF_B2 + (t - 128)] = b2[t - 128];

    // wait for CENTER only (ring keeps flying behind stages 1-2)
    asm volatile("cp.async.wait_group 1;" ::: "memory");
    __syncthreads();

    const int warp = t >> 5, lane = t & 31;
    const int gid = lane >> 2, t4 = lane & 3;

    // ---- Stage 1: mid[64px][64] = x @ W1 + b1  (3-term bf16 k16, K-SPLIT) ----
    // 16 warps: mt = warp>>2 (m-tile), nh = (warp>>1)&1 (4 ntiles), kh = warp&1 (K half)
    {
        const int mt = warp >> 2;
        const int nh = (warp >> 1) & 1;
        const int kh = warp & 1;
        const int m0 = mt * 16;
        const int px0 = m0 + gid, px1 = px0 + 8;
        const int sp0 = OFF_XH + (((px0 >> 3) + 1) * 10 + (px0 & 7) + 1) * XH_STRIDE;
        const int sp1 = OFF_XH + (((px1 >> 3) + 1) * 10 + (px1 & 7) + 1) * XH_STRIDE;
        float Dm[4][4], Dc[4][4];
        #pragma unroll
        for (int j = 0; j < 4; j++)
            #pragma unroll
            for (int i = 0; i < 4; i++) { Dm[j][i] = 0.f; Dc[j][i] = 0.f; }

        #pragma unroll 4
        for (int ss = 0; ss < 8; ss++) {
            const int k0 = (kh * 8 + ss) * 16;
            float2 p0 = *(const float2*)(s + sp0 + k0 + 2 * t4);
            float2 p1 = *(const float2*)(s + sp1 + k0 + 2 * t4);
            float2 p2 = *(const float2*)(s + sp0 + k0 + 8 + 2 * t4);
            float2 p3 = *(const float2*)(s + sp1 + k0 + 8 + 2 * t4);
            uint32_t ah[4], al[4];
            bf16_split_pair(p0.x, p0.y, ah[0], al[0]);
            bf16_split_pair(p1.x, p1.y, ah[1], al[1]);
            bf16_split_pair(p2.x, p2.y, ah[2], al[2]);
            bf16_split_pair(p3.x, p3.y, ah[3], al[3]);
            const int kw = (k0 >> 1) + t4;
            #pragma unroll
            for (int jj = 0; jj < 4; jj++) {
                int n = (nh * 4 + jj) * 8 + gid;
                uint32_t bh0 = su[OFF_W1H + n * W1P_STRIDE + kw];
                uint32_t bh1 = su[OFF_W1H + n * W1P_STRIDE + kw + 4];
                uint32_t bl0 = su[OFF_W1L + n * W1P_STRIDE + kw];
                uint32_t bl1 = su[OFF_W1L + n * W1P_STRIDE + kw + 4];
                mma_bf16(Dm[jj], ah[0], ah[1], ah[2], ah[3], bh0, bh1);
                mma_bf16(Dc[jj], al[0], al[1], al[2], al[3], bh0, bh1);
                mma_bf16(Dc[jj], ah[0], ah[1], ah[2], ah[3], bl0, bl1);
            }
        }
        // reduction: kh=0 writes partial to MID; kh=1 adds own + bias
        if (kh == 0) {
            #pragma unroll
            for (int jj = 0; jj < 4; jj++) {
                int n0 = (nh * 4 + jj) * 8 + 2 * t4;
                *(float2*)(s + OFF_MID + (m0 + gid) * MID_STRIDE + n0) =
                    make_float2(Dm[jj][0] + Dc[jj][0], Dm[jj][1] + Dc[jj][1]);
                *(float2*)(s + OFF_MID + (m0 + gid + 8) * MID_STRIDE + n0) =
                    make_float2(Dm[jj][2] + Dc[jj][2], Dm[jj][3] + Dc[jj][3]);
            }
        }
        __syncthreads();
        if (kh == 1) {
            #pragma unroll
            for (int jj = 0; jj < 4; jj++) {
                int n0 = (nh * 4 + jj) * 8 + 2 * t4;
                float bia0 = s[OFF_B1 + n0], bia1 = s[OFF_B1 + n0 + 1];
                float2 q0 = *(const float2*)(s + OFF_MID + (m0 + gid) * MID_STRIDE + n0);
                float2 q1 = *(const float2*)(s + OFF_MID + (m0 + gid + 8) * MID_STRIDE + n0);
                *(float2*)(s + OFF_MID + (m0 + gid) * MID_STRIDE + n0) =
                    make_float2(q0.x + Dm[jj][0] + Dc[jj][0] + bia0,
                                q0.y + Dm[jj][1] + Dc[jj][1] + bia1);
                *(float2*)(s + OFF_MID + (m0 + gid + 8) * MID_STRIDE + n0) =
                    make_float2(q1.x + Dm[jj][2] + Dc[jj][2] + bia0,
                                q1.y + Dm[jj][3] + Dc[jj][3] + bia1);
            }
        }
    }
    __syncthreads();

    // ---- Stage 2: wgt[64px][144] = mid @ W2 + b2  (3-term bf16 k16; wgt over W1) ----
    {
        const int m0 = (warp >> 2) * 16;
        const int nset = warp & 3;
        float Dm[5][4], Dc[5][4];
        #pragma unroll
        for (int j = 0; j < 5; j++)
            #pragma unroll
            for (int i = 0; i < 4; i++) { Dm[j][i] = 0.f; Dc[j][i] = 0.f; }

        #pragma unroll
        for (int k0 = 0; k0 < RED; k0 += 16) {
            float2 q0 = *(const float2*)(s + OFF_MID + (m0 + gid)     * MID_STRIDE + k0 + 2 * t4);
            float2 q1 = *(const float2*)(s + OFF_MID + (m0 + gid + 8) * MID_STRIDE + k0 + 2 * t4);
            float2 q2 = *(const float2*)(s + OFF_MID + (m0 + gid)     * MID_STRIDE + k0 + 8 + 2 * t4);
            float2 q3 = *(const float2*)(s + OFF_MID + (m0 + gid + 8) * MID_STRIDE + k0 + 8 + 2 * t4);
            uint32_t ah[4], al[4];
            bf16_split_pair(q0.x, q0.y, ah[0], al[0]);
            bf16_split_pair(q1.x, q1.y, ah[1], al[1]);
            bf16_split_pair(q2.x, q2.y, ah[2], al[2]);
            bf16_split_pair(q3.x, q3.y, ah[3], al[3]);
            const int kw = (k0 >> 1) + t4;
            #pragma unroll
            for (int jj = 0; jj < 5; jj++) {
                int j = nset + jj * 4;
                if (j < 18) {
                    int e = j * 8 + gid;
                    uint32_t bh0 = su[OFF_W2H + e * W2P_STRIDE + kw];
                    uint32_t bh1 = su[OFF_W2H + e * W2P_STRIDE + kw + 4];
                    uint32_t bl0 = su[OFF_W2L + e * W2P_STRIDE + kw];
                    uint32_t bl1 = su[OFF_W2L + e * W2P_STRIDE + kw + 4];
                    mma_bf16(Dm[jj], ah[0], ah[1], ah[2], ah[3], bh0, bh1);
                    mma_bf16(Dc[jj], al[0], al[1], al[2], al[3], bh0, bh1);
                    mma_bf16(Dc[jj], ah[0], ah[1], ah[2], ah[3], bl0, bl1);
                }
            }
        }
        #pragma unroll
        for (int jj = 0; jj < 5; jj++) {
            int j = nset + jj * 4;
            if (j < 18) {
                int e0 = j * 8 + 2 * t4;
                float bb0 = s[OFF_B2 + e0], bb1 = s[OFF_B2 + e0 + 1];
                s[OFF_WGT + (m0 + gid)     * WGT_STRIDE + e0]     = Dm[jj][0] + Dc[jj][0] + bb0;
                s[OFF_WGT + (m0 + gid)     * WGT_STRIDE + e0 + 1] = Dm[jj][1] + Dc[jj][1] + bb1;
                s[OFF_WGT + (m0 + gid + 8) * WGT_STRIDE + e0]     = Dm[jj][2] + Dc[jj][2] + bb0;
                s[OFF_WGT + (m0 + gid + 8) * WGT_STRIDE + e0 + 1] = Dm[jj][3] + Dc[jj][3] + bb1;
            }
        }
    }
    // ring must be landed before stage 3 reads the halo border
    asm volatile("cp.async.wait_group 0;" ::: "memory");
    __syncthreads();

    // ---- Stage 3: involution, float4 halo reads, direct STG ----
    {
        const int half = warp & 1, gset = warp >> 1;
        const int pr = half * 4 + (lane >> 3), pc = lane & 7;
        const int wbase = OFF_WGT + (pr * 8 + pc) * WGT_STRIDE;
        const int xb = OFF_XH + (pr * 10 + pc) * XH_STRIDE;   // tap (di=0,dj=0)
        float* op = out + ((size_t)((bb * HWDIM + h0 + pr) * HWDIM + (w0 + pc))) * CCH;
        #pragma unroll
        for (int gi = 0; gi < 2; gi++) {
            int g = gset * 2 + gi;
            float wv[9];
            #pragma unroll
            for (int k = 0; k < 9; k++) wv[k] = s[wbase + g * 9 + k];
            int F0g = g * 36;
            int ko0 = F0g >> 6;
            int cs0 = F0g & 63;
            int tc  = 64 - cs0;
            int di0 = (ko0 * 11) >> 5, dj0 = ko0 - 3 * di0;
            int ko1 = ko0 + 1;
            int di1 = (ko1 * 11) >> 5, dj1 = ko1 - 3 * di1;
            int A0 = xb + (di0 * 10 + dj0) * XH_STRIDE + cs0 * 4;
            int A1 = xb + (di1 * 10 + dj1) * XH_STRIDE - tc * 4;
            #pragma unroll
            for (int c = 0; c < 4; c++) {
                float acc[4] = {0.f, 0.f, 0.f, 0.f};
                #pragma unroll
                for (int j = 0; j < 9; j++) {
                    const int idx = c * 9 + j;
                    int addr = ((idx < tc) ? A0 : A1) + idx * 4;
                    const float4 xv = *(const float4*)(s + addr);
                    const int fl = idx * 4;
                    acc[(fl + 0) / 9 - c * 4] += wv[(fl + 0) % 9] * xv.x;
                    acc[(fl + 1) / 9 - c * 4] += wv[(fl + 1) % 9] * xv.y;
                    acc[(fl + 2) / 9 - c * 4] += wv[(fl + 2) % 9] * xv.z;
                    acc[(fl + 3) / 9 - c * 4] += wv[(fl + 3) % 9] * xv.w;
                }
                *(float4*)(op + g * 16 + c * 4) =
                    make_float4(acc[0], acc[1], acc[2], acc[3]);
            }
        }
    }
}

extern "C" void kernel_launch(void* const* d_in, const int* in_sizes, int n_in,
                              void* d_out, int out_size)
{
    (void)in_sizes; (void)n_in; (void)out_size;
    const float* x  = (const float*)d_in[0];
    const float* W1 = (const float*)d_in[1];
    const float* b1 = (const float*)d_in[2];
    const float* W2 = (const float*)d_in[3];
    const float* b2 = (const float*)d_in[4];
    float* out = (float*)d_out;

    cudaFuncSetAttribute(invo_mma_kernel,
                         cudaFuncAttributeMaxDynamicSharedMemorySize, SMEM_BYTES);
    dim3 grid(HWDIM / 8, HWDIM / 8, BATCH);   // (8, 8, 8) = 512 CTAs
    invo_mma_kernel<<<grid, NTHR, SMEM_BYTES>>>(x, W1, b1, W2, b2, out);
}